// round 8
// baseline (speedup 1.0000x reference)
#include <cuda_runtime.h>

namespace {
constexpr int NN   = 24;
constexpr int FIN  = 7;
constexpr int WD   = 64;
constexpr int FOUT = 13;
constexpr int MB   = 256;             // batch rows per GEMM CTA
constexpr long BMAX = 65536;
}

// Scratch state buffers, feature-major: Y[node][feat][batch]
__device__ float g_S1[NN * WD * BMAX];
__device__ float g_S2[NN * WD * BMAX];

// SMPL tree adjacency CSR (self + parent + children)
__constant__ int c_nbr_off[25] = {0,4,7,10,13,16,19,22,25,28,33,35,37,40,43,46,48,51,54,57,60,63,66,68,70};
__constant__ int c_nbr_lst[70] = {
    0,1,2,3, 1,0,4, 2,0,5, 3,0,6, 4,1,7, 5,2,8, 6,3,9, 7,4,10, 8,5,11,
    9,6,12,13,14, 10,7, 11,8, 12,9,15, 13,9,16, 14,9,17, 15,12, 16,13,18,
    17,14,19, 18,16,20, 19,17,21, 20,18,22, 21,19,23, 22,20, 23,21
};
__constant__ int c_nbr_m[70] = {
    0,0,0,0, 1,1,1, 2,2,2, 3,3,3, 4,4,4, 5,5,5, 6,6,6, 7,7,7, 8,8,8,
    9,9,9,9,9, 10,10, 11,11, 12,12,12, 13,13,13, 14,14,14, 15,15, 16,16,16,
    17,17,17, 18,18,18, 19,19,19, 20,20,20, 21,21,21, 22,22, 23,23
};

// packed 2xfp32 helpers
__device__ __forceinline__ unsigned long long dup2(float s) {
    unsigned long long d;
    asm("mov.b64 %0, {%1, %1};" : "=l"(d) : "r"(__float_as_uint(s)));
    return d;
}
__device__ __forceinline__ void fma2(unsigned long long& d,
                                     unsigned long long a, unsigned long long b) {
    asm("fma.rn.f32x2 %0, %1, %2, %0;" : "+l"(d) : "l"(a), "l"(b));
}
__device__ __forceinline__ float2 unpk(unsigned long long v) {
    float2 r;
    asm("mov.b64 {%0, %1}, %2;" : "=f"(r.x), "=f"(r.y) : "l"(v));
    return r;
}

// ---------------- G1: L0 matmul (K=7), x[b][n][i] (masked) -> Y1[n][o][b] -----
__global__ __launch_bounds__(MB, 2)
void gemm_l0(const float* __restrict__ x, const float* __restrict__ w0,
             float* __restrict__ Yout, int B)
{
    extern __shared__ float sm[];
    float* Xs = sm;                 // [7][256]
    float* Ws = sm + FIN * MB;      // [7][64]

    const int n  = blockIdx.y;
    const long b0 = (long)blockIdx.x * MB;
    const int tid = threadIdx.x;
    const int og = tid & 7;         // o-group (8 outputs)
    const int bg = tid >> 3;        // batch group (8 rows)

    // FIX round 7: FIN*WD = 448 > blockDim (256) -> must loop, not single guard
    for (int e = tid; e < FIN * WD; e += MB) Ws[e] = w0[n * FIN * WD + e];
    const float msk = (n == 0) ? 0.0f : 1.0f;
    for (int e = tid; e < FIN * MB; e += MB) {
        const int i = e >> 8, bl = e & (MB - 1);
        Xs[e] = msk * x[(b0 + bl) * (NN * FIN) + n * FIN + i];
    }
    __syncthreads();

    unsigned long long acc[8][4];
    #pragma unroll
    for (int b = 0; b < 8; b++)
        #pragma unroll
        for (int j = 0; j < 4; j++) acc[b][j] = 0ull;

    #pragma unroll
    for (int i = 0; i < FIN; i++) {
        const ulonglong2 wa = *reinterpret_cast<const ulonglong2*>(Ws + i * WD + og * 8);
        const ulonglong2 wb = *reinterpret_cast<const ulonglong2*>(Ws + i * WD + og * 8 + 4);
        const float4 xv0 = *reinterpret_cast<const float4*>(Xs + i * MB + bg * 8);
        const float4 xv1 = *reinterpret_cast<const float4*>(Xs + i * MB + bg * 8 + 4);
        const float xr[8] = {xv0.x, xv0.y, xv0.z, xv0.w, xv1.x, xv1.y, xv1.z, xv1.w};
        #pragma unroll
        for (int b = 0; b < 8; b++) {
            const unsigned long long xd = dup2(xr[b]);
            fma2(acc[b][0], xd, wa.x);
            fma2(acc[b][1], xd, wa.y);
            fma2(acc[b][2], xd, wb.x);
            fma2(acc[b][3], xd, wb.y);
        }
    }
    // epilogue: Y[n][o][b]; acc[b][j] holds features {og*8+2j, og*8+2j+1}
    #pragma unroll
    for (int j = 0; j < 4; j++) {
        float lo[8], hi[8];
        #pragma unroll
        for (int b = 0; b < 8; b++) { float2 p = unpk(acc[b][j]); lo[b] = p.x; hi[b] = p.y; }
        const int o = og * 8 + 2 * j;
        float* p0 = Yout + (size_t)(n * WD + o) * B + b0 + bg * 8;
        *reinterpret_cast<float4*>(p0)     = make_float4(lo[0], lo[1], lo[2], lo[3]);
        *reinterpret_cast<float4*>(p0 + 4) = make_float4(lo[4], lo[5], lo[6], lo[7]);
        float* p1 = p0 + B;
        *reinterpret_cast<float4*>(p1)     = make_float4(hi[0], hi[1], hi[2], hi[3]);
        *reinterpret_cast<float4*>(p1 + 4) = make_float4(hi[4], hi[5], hi[6], hi[7]);
    }
}

// ------- G2/G3: fused (prev-layer agg + bias + relu) prologue, then 64x64 GEMM
__global__ __launch_bounds__(MB, 2)
void gemm_hidden(const float* __restrict__ Yprev, const float* __restrict__ w,
                 const float* __restrict__ adjw_prev, const float* __restrict__ b_prev,
                 float* __restrict__ Yout, int B)
{
    extern __shared__ float sm[];
    float* Xs    = sm;                       // [64][256]
    float* Ws    = Xs + WD * MB;             // [64][64]
    float* aeffs = Ws + WD * WD;             // <=5
    float* biass = aeffs + 8;                // 64

    const int n  = blockIdx.y;
    const long b0 = (long)blockIdx.x * MB;
    const int tid = threadIdx.x;
    const int og = tid & 7;
    const int bg = tid >> 3;

    const int s   = c_nbr_off[n];
    const int deg = c_nbr_off[n + 1] - s;

    if (tid < deg) aeffs[tid] = adjw_prev[n * NN + c_nbr_lst[s + tid]];
    if (tid < WD)  biass[tid] = b_prev[tid];
    for (int e = tid; e < WD * WD; e += MB) Ws[e] = w[n * WD * WD + e];
    __syncthreads();

    // prologue: Xs[i][b] = relu(bias[i] + sum_k aeff * Yprev[k][i][b])
    for (int e = tid; e < WD * MB; e += MB) {
        const int i = e >> 8, bl = e & (MB - 1);
        float acc = biass[i];
        for (int kk = 0; kk < deg; kk++) {
            const int k = c_nbr_lst[s + kk];
            acc = fmaf(aeffs[kk], Yprev[(size_t)(k * WD + i) * B + b0 + bl], acc);
        }
        Xs[e] = fmaxf(acc, 0.0f);
    }
    __syncthreads();

    unsigned long long acc[8][4];
    #pragma unroll
    for (int b = 0; b < 8; b++)
        #pragma unroll
        for (int j = 0; j < 4; j++) acc[b][j] = 0ull;

    #pragma unroll 8
    for (int i = 0; i < WD; i++) {
        const ulonglong2 wa = *reinterpret_cast<const ulonglong2*>(Ws + i * WD + og * 8);
        const ulonglong2 wb = *reinterpret_cast<const ulonglong2*>(Ws + i * WD + og * 8 + 4);
        const float4 xv0 = *reinterpret_cast<const float4*>(Xs + i * MB + bg * 8);
        const float4 xv1 = *reinterpret_cast<const float4*>(Xs + i * MB + bg * 8 + 4);
        const float xr[8] = {xv0.x, xv0.y, xv0.z, xv0.w, xv1.x, xv1.y, xv1.z, xv1.w};
        #pragma unroll
        for (int b = 0; b < 8; b++) {
            const unsigned long long xd = dup2(xr[b]);
            fma2(acc[b][0], xd, wa.x);
            fma2(acc[b][1], xd, wa.y);
            fma2(acc[b][2], xd, wb.x);
            fma2(acc[b][3], xd, wb.y);
        }
    }
    #pragma unroll
    for (int j = 0; j < 4; j++) {
        float lo[8], hi[8];
        #pragma unroll
        for (int b = 0; b < 8; b++) { float2 p = unpk(acc[b][j]); lo[b] = p.x; hi[b] = p.y; }
        const int o = og * 8 + 2 * j;
        float* p0 = Yout + (size_t)(n * WD + o) * B + b0 + bg * 8;
        *reinterpret_cast<float4*>(p0)     = make_float4(lo[0], lo[1], lo[2], lo[3]);
        *reinterpret_cast<float4*>(p0 + 4) = make_float4(lo[4], lo[5], lo[6], lo[7]);
        float* p1 = p0 + B;
        *reinterpret_cast<float4*>(p1)     = make_float4(hi[0], hi[1], hi[2], hi[3]);
        *reinterpret_cast<float4*>(p1 + 4) = make_float4(hi[4], hi[5], hi[6], hi[7]);
    }
}

// ------- G4: agg2 prologue + L3 matmul (N=13) -> Y4[n][o][b] ------------------
__global__ __launch_bounds__(MB, 2)
void gemm_l3(const float* __restrict__ Yprev, const float* __restrict__ w3,
             const float* __restrict__ adjw_prev, const float* __restrict__ b_prev,
             float* __restrict__ Yout, int B)
{
    extern __shared__ float sm[];
    float* Xs    = sm;                       // [64][256]
    float* Ws    = Xs + WD * MB;             // [64][16] padded
    float* aeffs = Ws + WD * 16;
    float* biass = aeffs + 8;                // 64

    const int n  = blockIdx.y;
    const long b0 = (long)blockIdx.x * MB;
    const int tid = threadIdx.x;

    const int s   = c_nbr_off[n];
    const int deg = c_nbr_off[n + 1] - s;

    if (tid < deg) aeffs[tid] = adjw_prev[n * NN + c_nbr_lst[s + tid]];
    if (tid < WD)  biass[tid] = b_prev[tid];
    for (int e = tid; e < WD * 16; e += MB) {
        const int i = e >> 4, o = e & 15;
        Ws[e] = (o < FOUT) ? w3[(n * WD + i) * FOUT + o] : 0.0f;
    }
    __syncthreads();

    for (int e = tid; e < WD * MB; e += MB) {
        const int i = e >> 8, bl = e & (MB - 1);
        float acc = biass[i];
        for (int kk = 0; kk < deg; kk++) {
            const int k = c_nbr_lst[s + kk];
            acc = fmaf(aeffs[kk], Yprev[(size_t)(k * WD + i) * B + b0 + bl], acc);
        }
        Xs[e] = fmaxf(acc, 0.0f);
    }
    __syncthreads();

    const int o   = tid & 15;       // 13 active
    const int bgg = tid >> 4;       // 16 groups x 16 rows
    float acc[16];
    #pragma unroll
    for (int b = 0; b < 16; b++) acc[b] = 0.f;
    #pragma unroll 4
    for (int i = 0; i < WD; i++) {
        const float wv = Ws[i * 16 + o];
        const float* xp = Xs + i * MB + bgg * 16;
        #pragma unroll
        for (int b = 0; b < 16; b++) acc[b] = fmaf(xp[b], wv, acc[b]);
    }
    if (o < FOUT) {
        float* p = Yout + (size_t)(n * FOUT + o) * B + b0 + bgg * 16;
        #pragma unroll
        for (int q = 0; q < 4; q++)
            *reinterpret_cast<float4*>(p + q * 4) =
                make_float4(acc[q*4], acc[q*4+1], acc[q*4+2], acc[q*4+3]);
    }
}

// ------- G5: final agg3 + b3 (no relu) + transpose to out[b][24][13] ----------
__global__ __launch_bounds__(MB, 1)
void final_agg(const float* __restrict__ Y4, const float* __restrict__ adjw3,
               const float* __restrict__ b3, float* __restrict__ out, int B)
{
    extern __shared__ float sm[];
    constexpr int BC = 128;          // batch chunk
    constexpr int RP = 313;          // padded row (24*13=312)
    float* outS   = sm;              // [128][313]
    float* aeff3s = outS + BC * RP;  // 70
    float* b3s    = aeff3s + 70;     // 13

    const long b0 = (long)blockIdx.x * BC;
    const int tid = threadIdx.x;

    if (tid < 70) aeff3s[tid] = adjw3[c_nbr_m[tid] * NN + c_nbr_lst[tid]];
    if (tid < FOUT) b3s[tid] = b3[tid];
    __syncthreads();

    for (int e = tid; e < NN * FOUT * BC; e += MB) {
        const int bl = e & (BC - 1);
        const int mo = e >> 7;
        const int m = mo / FOUT, o = mo - m * FOUT;
        float v = b3s[o];
        const int s = c_nbr_off[m], en = c_nbr_off[m + 1];
        for (int cc = s; cc < en; cc++)
            v = fmaf(aeff3s[cc], Y4[(size_t)(c_nbr_lst[cc] * FOUT + o) * B + b0 + bl], v);
        outS[bl * RP + mo] = v;
    }
    __syncthreads();

    const int wid = tid >> 5, lane = tid & 31;
    for (int r = wid; r < BC; r += 8)
        for (int j = lane; j < NN * FOUT; j += 32)
            out[(b0 + r) * (NN * FOUT) + j] = outS[r * RP + j];
}

extern "C" void kernel_launch(void* const* d_in, const int* in_sizes, int n_in,
                              void* d_out, int out_size) {
    const float* x   = (const float*)d_in[0];
    const float* w0  = (const float*)d_in[1];
    const float* w1  = (const float*)d_in[2];
    const float* w2  = (const float*)d_in[3];
    const float* w3  = (const float*)d_in[4];
    const float* aw0 = (const float*)d_in[5];
    const float* aw1 = (const float*)d_in[6];
    const float* aw2 = (const float*)d_in[7];
    const float* aw3 = (const float*)d_in[8];
    const float* b0  = (const float*)d_in[9];
    const float* b1  = (const float*)d_in[10];
    const float* b2  = (const float*)d_in[11];
    const float* b3  = (const float*)d_in[12];
    float* out = (float*)d_out;

    const int B = in_sizes[0] / (NN * FIN);

    float *pS1 = nullptr, *pS2 = nullptr;
    cudaGetSymbolAddress((void**)&pS1, g_S1);
    cudaGetSymbolAddress((void**)&pS2, g_S2);

    const size_t smL0 = (size_t)(FIN * MB + FIN * WD) * sizeof(float);
    const size_t smH  = (size_t)(WD * MB + WD * WD + 8 + WD) * sizeof(float);
    const size_t smL3 = (size_t)(WD * MB + WD * 16 + 8 + WD) * sizeof(float);
    const size_t smF  = (size_t)(128 * 313 + 70 + 16) * sizeof(float);

    cudaFuncSetAttribute(gemm_hidden, cudaFuncAttributeMaxDynamicSharedMemorySize, (int)smH);
    cudaFuncSetAttribute(gemm_l3,     cudaFuncAttributeMaxDynamicSharedMemorySize, (int)smL3);
    cudaFuncSetAttribute(final_agg,   cudaFuncAttributeMaxDynamicSharedMemorySize, (int)smF);

    dim3 gG(B / MB, NN);
    gemm_l0    <<<gG, MB, smL0>>>(x, w0, pS1, B);
    gemm_hidden<<<gG, MB, smH>>>(pS1, w1, aw0, b0, pS2, B);
    gemm_hidden<<<gG, MB, smH>>>(pS2, w2, aw1, b1, pS1, B);
    gemm_l3    <<<gG, MB, smL3>>>(pS1, w3, aw2, b2, pS2, B);
    final_agg  <<<B / 128, MB, smF>>>(pS2, aw3, b3, out, B);
}

// round 9
// speedup vs baseline: 2.9590x; 2.9590x over previous
#include <cuda_runtime.h>

namespace {
constexpr int NN   = 24;   // nodes
constexpr int FIN  = 7;    // input features
constexpr int WD   = 64;   // hidden width
constexpr int FOUT = 13;   // output features
constexpr int TB   = 8;    // batch tile per CTA
constexpr int HB   = 4;    // batch rows per thread
constexpr int NT   = 384;  // 24 nodes * 2 batch-halves * 8 o-groups
constexpr int STATE = NN * WD;  // 1536 floats per batch row
}

// SMPL tree adjacency CSR (self + parent + children)
__constant__ int c_nbr_off[25] = {0,4,7,10,13,16,19,22,25,28,33,35,37,40,43,46,48,51,54,57,60,63,66,68,70};
__constant__ int c_nbr_lst[70] = {
    0,1,2,3, 1,0,4, 2,0,5, 3,0,6, 4,1,7, 5,2,8, 6,3,9, 7,4,10, 8,5,11,
    9,6,12,13,14, 10,7, 11,8, 12,9,15, 13,9,16, 14,9,17, 15,12, 16,13,18,
    17,14,19, 18,16,20, 19,17,21, 20,18,22, 21,19,23, 22,20, 23,21
};
__constant__ int c_nbr_m[70] = {
    0,0,0,0, 1,1,1, 2,2,2, 3,3,3, 4,4,4, 5,5,5, 6,6,6, 7,7,7, 8,8,8,
    9,9,9,9,9, 10,10, 11,11, 12,12,12, 13,13,13, 14,14,14, 15,15, 16,16,16,
    17,17,17, 18,18,18, 19,19,19, 20,20,20, 21,21,21, 22,22, 23,23
};

// packed 2xfp32 helpers (Blackwell f32x2; PTX-only)
__device__ __forceinline__ unsigned long long dup2(float s) {
    unsigned long long d;
    asm("mov.b64 %0, {%1, %1};" : "=l"(d) : "r"(__float_as_uint(s)));
    return d;
}
__device__ __forceinline__ void fma2(unsigned long long& d,
                                     unsigned long long a, unsigned long long b) {
    asm("fma.rn.f32x2 %0, %1, %2, %0;" : "+l"(d) : "l"(a), "l"(b));
}

__global__ __launch_bounds__(NT, 2)
void gnn_fused(const float* __restrict__ x,
               const float* __restrict__ w0, const float* __restrict__ w1,
               const float* __restrict__ w2, const float* __restrict__ w3,
               const float* __restrict__ aw0, const float* __restrict__ aw1,
               const float* __restrict__ aw2, const float* __restrict__ aw3,
               const float* __restrict__ b0, const float* __restrict__ b1,
               const float* __restrict__ b2, const float* __restrict__ b3,
               float* __restrict__ out)
{
    extern __shared__ float smem[];
    float* bufA = smem;                    // TB*STATE = 12288 floats
    float* bufB = bufA + TB * STATE;       // TB*STATE
    float* xin  = bufB;                    // alias: xin dead once L0 agg writes bufB
    float* aeff = bufB + TB * STATE;       // 4*70 masked adjacency weights
    float* bias = aeff + 4 * 70;           // 3*64 + 13

    const int tid = threadIdx.x;
    const long brow0 = (long)blockIdx.x * TB;

    // Stage masked adjacency weights (adjw * adj, nonzeros only)
    for (int idx = tid; idx < 4 * 70; idx += NT) {
        int l = idx / 70, e = idx - l * 70;
        const float* aw = (l == 0) ? aw0 : (l == 1) ? aw1 : (l == 2) ? aw2 : aw3;
        aeff[idx] = aw[c_nbr_m[e] * NN + c_nbr_lst[e]];
    }
    // Stage biases
    for (int idx = tid; idx < 3 * WD + FOUT; idx += NT) {
        float v;
        if      (idx <     WD) v = b0[idx];
        else if (idx < 2 * WD) v = b1[idx - WD];
        else if (idx < 3 * WD) v = b2[idx - 2 * WD];
        else                   v = b3[idx - 3 * WD];
        bias[idx] = v;
    }
    // Stage input tile with root-node mask (node 0 zeroed)
    for (int idx = tid; idx < TB * NN * FIN; idx += NT) {
        int j = idx % (NN * FIN);
        float v = x[brow0 * (NN * FIN) + idx];
        if (j < FIN) v = 0.0f;  // root joint masked
        xin[idx] = v;
    }
    __syncthreads();

    // Thread map: 16 lanes (2 bh x 8 og) per node; two nodes per warp.
    const int n  = tid >> 4;        // node 0..23
    const int bh = (tid >> 3) & 1;  // batch half
    const int og = tid & 7;         // output group
    const int o0 = og * 8;          // 8 outputs per thread
    const int bb = bh * HB;         // first batch row

    // ---- Layer 0 matmul: xin[b][n][0:7] @ w0[n][7][64] -> bufA ----
    {
        float4 aL[HB], aH[HB];
        #pragma unroll
        for (int b = 0; b < HB; b++) {
            aL[b] = make_float4(0.f, 0.f, 0.f, 0.f);
            aH[b] = make_float4(0.f, 0.f, 0.f, 0.f);
        }
        #pragma unroll
        for (int i = 0; i < FIN; i++) {
            const float4 wL = __ldg(reinterpret_cast<const float4*>(w0 + (n * FIN + i) * WD + o0));
            const float4 wH = __ldg(reinterpret_cast<const float4*>(w0 + (n * FIN + i) * WD + o0 + 4));
            #pragma unroll
            for (int b = 0; b < HB; b++) {
                const float xv = xin[(bb + b) * (NN * FIN) + n * FIN + i];
                aL[b].x = fmaf(xv, wL.x, aL[b].x);
                aL[b].y = fmaf(xv, wL.y, aL[b].y);
                aL[b].z = fmaf(xv, wL.z, aL[b].z);
                aL[b].w = fmaf(xv, wL.w, aL[b].w);
                aH[b].x = fmaf(xv, wH.x, aH[b].x);
                aH[b].y = fmaf(xv, wH.y, aH[b].y);
                aH[b].z = fmaf(xv, wH.z, aH[b].z);
                aH[b].w = fmaf(xv, wH.w, aH[b].w);
            }
        }
        __syncthreads();  // all xin reads done (xin aliases bufB, written next phase)
        #pragma unroll
        for (int b = 0; b < HB; b++) {
            float* dp = bufA + (bb + b) * STATE + n * WD + o0;
            *reinterpret_cast<float4*>(dp)     = aL[b];
            *reinterpret_cast<float4*>(dp + 4) = aH[b];
        }
    }
    __syncthreads();

    // Sparse tree aggregation + bias (+ReLU): h -> dst
    auto agg = [&](const float* __restrict__ h, const float* __restrict__ ae,
                   const float* __restrict__ bi, float* __restrict__ dst, bool relu) {
        const int s = c_nbr_off[n], e = c_nbr_off[n + 1];
        const float4 bvL = *reinterpret_cast<const float4*>(bi + o0);
        const float4 bvH = *reinterpret_cast<const float4*>(bi + o0 + 4);
        #pragma unroll
        for (int b = 0; b < HB; b++) {
            float4 aL = bvL, aH = bvH;
            for (int k = s; k < e; k++) {
                const float aw = ae[k];
                const float* hp = h + (bb + b) * STATE + c_nbr_lst[k] * WD + o0;
                const float4 hL = *reinterpret_cast<const float4*>(hp);
                const float4 hH = *reinterpret_cast<const float4*>(hp + 4);
                aL.x = fmaf(aw, hL.x, aL.x);
                aL.y = fmaf(aw, hL.y, aL.y);
                aL.z = fmaf(aw, hL.z, aL.z);
                aL.w = fmaf(aw, hL.w, aL.w);
                aH.x = fmaf(aw, hH.x, aH.x);
                aH.y = fmaf(aw, hH.y, aH.y);
                aH.z = fmaf(aw, hH.z, aH.z);
                aH.w = fmaf(aw, hH.w, aH.w);
            }
            if (relu) {
                aL.x = fmaxf(aL.x, 0.f); aL.y = fmaxf(aL.y, 0.f);
                aL.z = fmaxf(aL.z, 0.f); aL.w = fmaxf(aL.w, 0.f);
                aH.x = fmaxf(aH.x, 0.f); aH.y = fmaxf(aH.y, 0.f);
                aH.z = fmaxf(aH.z, 0.f); aH.w = fmaxf(aH.w, 0.f);
            }
            float* dp = dst + (bb + b) * STATE + n * WD + o0;
            *reinterpret_cast<float4*>(dp)     = aL;
            *reinterpret_cast<float4*>(dp + 4) = aH;
        }
    };

    // Hidden-layer per-node matmul with f32x2, o-tile 8, b-tile 4.
    // acc[b] = 4 packed pairs covering o0..o0+7.
    auto mm64 = [&](const float* __restrict__ src, const float* __restrict__ wgt,
                    float* __restrict__ dst) {
        unsigned long long acc[HB][4];
        #pragma unroll
        for (int b = 0; b < HB; b++)
            #pragma unroll
            for (int j = 0; j < 4; j++) acc[b][j] = 0ull;
        const float* wrow = wgt + n * WD * WD + o0;
        const float* abase = src + n * WD;
        #pragma unroll 2
        for (int i = 0; i < WD; i += 4) {
            float4 xv[HB];
            #pragma unroll
            for (int b = 0; b < HB; b++)
                xv[b] = *reinterpret_cast<const float4*>(abase + (bb + b) * STATE + i);
            // rows i, i+1
            {
                const ulonglong2 wa = __ldg(reinterpret_cast<const ulonglong2*>(wrow + (i + 0) * WD));
                const ulonglong2 wb = __ldg(reinterpret_cast<const ulonglong2*>(wrow + (i + 0) * WD + 4));
                const ulonglong2 wc = __ldg(reinterpret_cast<const ulonglong2*>(wrow + (i + 1) * WD));
                const ulonglong2 wd = __ldg(reinterpret_cast<const ulonglong2*>(wrow + (i + 1) * WD + 4));
                #pragma unroll
                for (int b = 0; b < HB; b++) {
                    const unsigned long long x0 = dup2(xv[b].x);
                    fma2(acc[b][0], x0, wa.x);
                    fma2(acc[b][1], x0, wa.y);
                    fma2(acc[b][2], x0, wb.x);
                    fma2(acc[b][3], x0, wb.y);
                    const unsigned long long x1 = dup2(xv[b].y);
                    fma2(acc[b][0], x1, wc.x);
                    fma2(acc[b][1], x1, wc.y);
                    fma2(acc[b][2], x1, wd.x);
                    fma2(acc[b][3], x1, wd.y);
                }
            }
            // rows i+2, i+3
            {
                const ulonglong2 wa = __ldg(reinterpret_cast<const ulonglong2*>(wrow + (i + 2) * WD));
                const ulonglong2 wb = __ldg(reinterpret_cast<const ulonglong2*>(wrow + (i + 2) * WD + 4));
                const ulonglong2 wc = __ldg(reinterpret_cast<const ulonglong2*>(wrow + (i + 3) * WD));
                const ulonglong2 wd = __ldg(reinterpret_cast<const ulonglong2*>(wrow + (i + 3) * WD + 4));
                #pragma unroll
                for (int b = 0; b < HB; b++) {
                    const unsigned long long x2 = dup2(xv[b].z);
                    fma2(acc[b][0], x2, wa.x);
                    fma2(acc[b][1], x2, wa.y);
                    fma2(acc[b][2], x2, wb.x);
                    fma2(acc[b][3], x2, wb.y);
                    const unsigned long long x3 = dup2(xv[b].w);
                    fma2(acc[b][0], x3, wc.x);
                    fma2(acc[b][1], x3, wc.y);
                    fma2(acc[b][2], x3, wd.x);
                    fma2(acc[b][3], x3, wd.y);
                }
            }
        }
        #pragma unroll
        for (int b = 0; b < HB; b++) {
            float* dp = dst + (bb + b) * STATE + n * WD + o0;
            *reinterpret_cast<ulonglong2*>(dp)     = make_ulonglong2(acc[b][0], acc[b][1]);
            *reinterpret_cast<ulonglong2*>(dp + 4) = make_ulonglong2(acc[b][2], acc[b][3]);
        }
    };

    agg(bufA, aeff + 0, bias + 0, bufB, true);        // L0 agg
    __syncthreads();
    mm64(bufB, w1, bufA);                              // L1 matmul
    __syncthreads();
    agg(bufA, aeff + 70, bias + WD, bufB, true);       // L1 agg
    __syncthreads();
    mm64(bufB, w2, bufA);                              // L2 matmul
    __syncthreads();
    agg(bufA, aeff + 140, bias + 2 * WD, bufB, true);  // L2 agg
    __syncthreads();

    // ---- Layer 3 matmul: bufB[b][n][0:64] @ w3[n][64][13] -> bufA (stride WD) ----
    if (tid < NN * FOUT) {
        const int n3 = tid / FOUT, o3 = tid - n3 * FOUT;
        float acc[TB];
        #pragma unroll
        for (int b = 0; b < TB; b++) acc[b] = 0.f;
        #pragma unroll 4
        for (int i = 0; i < WD; i++) {
            const float wv = __ldg(w3 + (n3 * WD + i) * FOUT + o3);
            #pragma unroll
            for (int b = 0; b < TB; b++)
                acc[b] = fmaf(bufB[b * STATE + n3 * WD + i], wv, acc[b]);
        }
        #pragma unroll
        for (int b = 0; b < TB; b++)
            bufA[b * STATE + n3 * WD + o3] = acc[b];
    }
    __syncthreads();

    // ---- Layer 3 aggregation + bias, store to global ----
    if (tid < NN * FOUT) {
        const int n3 = tid / FOUT, o3 = tid - n3 * FOUT;
        const int s = c_nbr_off[n3], e = c_nbr_off[n3 + 1];
        const float bv3 = bias[3 * WD + o3];
        #pragma unroll
        for (int b = 0; b < TB; b++) {
            float a0 = bv3;
            for (int k = s; k < e; k++)
                a0 = fmaf(aeff[210 + k], bufA[b * STATE + c_nbr_lst[k] * WD + o3], a0);
            out[(brow0 + b) * (NN * FOUT) + n3 * FOUT + o3] = a0;
        }
    }
}

extern "C" void kernel_launch(void* const* d_in, const int* in_sizes, int n_in,
                              void* d_out, int out_size) {
    const float* x   = (const float*)d_in[0];
    const float* w0  = (const float*)d_in[1];
    const float* w1  = (const float*)d_in[2];
    const float* w2  = (const float*)d_in[3];
    const float* w3  = (const float*)d_in[4];
    const float* aw0 = (const float*)d_in[5];
    const float* aw1 = (const float*)d_in[6];
    const float* aw2 = (const float*)d_in[7];
    const float* aw3 = (const float*)d_in[8];
    const float* b0  = (const float*)d_in[9];
    const float* b1  = (const float*)d_in[10];
    const float* b2  = (const float*)d_in[11];
    const float* b3  = (const float*)d_in[12];
    float* out = (float*)d_out;

    const int B = in_sizes[0] / (NN * FIN);
    const int grid = (B + TB - 1) / TB;
    const size_t smem_bytes =
        (size_t)(2 * TB * STATE + 4 * 70 + 3 * WD + FOUT) * sizeof(float);

    cudaFuncSetAttribute(gnn_fused, cudaFuncAttributeMaxDynamicSharedMemorySize,
                         (int)smem_bytes);
    gnn_fused<<<grid, NT, smem_bytes>>>(x, w0, w1, w2, w3,
                                        aw0, aw1, aw2, aw3,
                                        b0, b1, b2, b3, out);
}

// round 10
// speedup vs baseline: 4.1433x; 1.4002x over previous
#include <cuda_runtime.h>

namespace {
constexpr int NN   = 24;   // nodes
constexpr int FIN  = 7;    // input features
constexpr int WD   = 64;   // hidden width
constexpr int FOUT = 13;   // output features
constexpr int TB   = 6;    // batch tile per CTA (3 CTAs/SM)
constexpr int NT   = 384;  // 24 nodes * 16 o-groups
constexpr int STATE = NN * WD;  // 1536 floats per batch row
}

// SMPL tree adjacency CSR (self + parent + children)
__constant__ int c_nbr_off[25] = {0,4,7,10,13,16,19,22,25,28,33,35,37,40,43,46,48,51,54,57,60,63,66,68,70};
__constant__ int c_nbr_lst[70] = {
    0,1,2,3, 1,0,4, 2,0,5, 3,0,6, 4,1,7, 5,2,8, 6,3,9, 7,4,10, 8,5,11,
    9,6,12,13,14, 10,7, 11,8, 12,9,15, 13,9,16, 14,9,17, 15,12, 16,13,18,
    17,14,19, 18,16,20, 19,17,21, 20,18,22, 21,19,23, 22,20, 23,21
};
__constant__ int c_nbr_m[70] = {
    0,0,0,0, 1,1,1, 2,2,2, 3,3,3, 4,4,4, 5,5,5, 6,6,6, 7,7,7, 8,8,8,
    9,9,9,9,9, 10,10, 11,11, 12,12,12, 13,13,13, 14,14,14, 15,15, 16,16,16,
    17,17,17, 18,18,18, 19,19,19, 20,20,20, 21,21,21, 22,22, 23,23
};

// packed 2xfp32 helpers (Blackwell f32x2; PTX-only)
__device__ __forceinline__ unsigned long long dup2(float s) {
    unsigned long long d;
    asm("mov.b64 %0, {%1, %1};" : "=l"(d) : "r"(__float_as_uint(s)));
    return d;
}
__device__ __forceinline__ void fma2(unsigned long long& d,
                                     unsigned long long a, unsigned long long b) {
    asm("fma.rn.f32x2 %0, %1, %2, %0;" : "+l"(d) : "l"(a), "l"(b));
}

__global__ __launch_bounds__(NT, 3)
void gnn_fused(const float* __restrict__ x,
               const float* __restrict__ w0, const float* __restrict__ w1,
               const float* __restrict__ w2, const float* __restrict__ w3,
               const float* __restrict__ aw0, const float* __restrict__ aw1,
               const float* __restrict__ aw2, const float* __restrict__ aw3,
               const float* __restrict__ b0, const float* __restrict__ b1,
               const float* __restrict__ b2, const float* __restrict__ b3,
               float* __restrict__ out, int B)
{
    extern __shared__ float smem[];
    float* bufA = smem;                    // TB*STATE floats
    float* bufB = bufA + TB * STATE;       // TB*STATE
    float* xin  = bufB;                    // alias: xin dead once L0 agg writes bufB
    float* aeff = bufB + TB * STATE;       // 4*70 masked adjacency weights
    float* bias = aeff + 4 * 70;           // 3*64 + 13

    const int tid = threadIdx.x;
    const long brow0 = (long)blockIdx.x * TB;

    // Stage masked adjacency weights (adjw * adj, nonzeros only)
    for (int idx = tid; idx < 4 * 70; idx += NT) {
        int l = idx / 70, e = idx - l * 70;
        const float* aw = (l == 0) ? aw0 : (l == 1) ? aw1 : (l == 2) ? aw2 : aw3;
        aeff[idx] = aw[c_nbr_m[e] * NN + c_nbr_lst[e]];
    }
    // Stage biases
    for (int idx = tid; idx < 3 * WD + FOUT; idx += NT) {
        float v;
        if      (idx <     WD) v = b0[idx];
        else if (idx < 2 * WD) v = b1[idx - WD];
        else if (idx < 3 * WD) v = b2[idx - 2 * WD];
        else                   v = b3[idx - 3 * WD];
        bias[idx] = v;
    }
    // Stage input tile with root-node mask; guard the B-remainder tile
    for (int idx = tid; idx < TB * NN * FIN; idx += NT) {
        const int bl = idx / (NN * FIN);
        const int j  = idx % (NN * FIN);
        float v = 0.0f;
        if (brow0 + bl < B && j >= FIN)   // node 0 masked
            v = x[(brow0 + bl) * (NN * FIN) + j];
        xin[idx] = v;
    }
    __syncthreads();

    const int n  = tid >> 4;        // node 0..23
    const int o0 = (tid & 15) * 4;  // output feature group

    // ---- Layer 0 matmul: xin[b][n][0:7] @ w0[n][7][64] -> bufA ----
    {
        float4 acc[TB];
        #pragma unroll
        for (int b = 0; b < TB; b++) acc[b] = make_float4(0.f, 0.f, 0.f, 0.f);
        #pragma unroll
        for (int i = 0; i < FIN; i++) {
            const float4 wv = __ldg(reinterpret_cast<const float4*>(w0 + (n * FIN + i) * WD + o0));
            #pragma unroll
            for (int b = 0; b < TB; b++) {
                const float xv = xin[b * (NN * FIN) + n * FIN + i];
                acc[b].x = fmaf(xv, wv.x, acc[b].x);
                acc[b].y = fmaf(xv, wv.y, acc[b].y);
                acc[b].z = fmaf(xv, wv.z, acc[b].z);
                acc[b].w = fmaf(xv, wv.w, acc[b].w);
            }
        }
        __syncthreads();   // xin reads done (xin aliases bufB)
        #pragma unroll
        for (int b = 0; b < TB; b++)
            *reinterpret_cast<float4*>(bufA + b * STATE + n * WD + o0) = acc[b];
    }
    __syncthreads();

    // Sparse tree aggregation + bias (+ReLU): h -> dst
    auto agg = [&](const float* __restrict__ h, const float* __restrict__ ae,
                   const float* __restrict__ bi, float* __restrict__ dst, bool relu) {
        const int s = c_nbr_off[n], e = c_nbr_off[n + 1];
        const float4 bv = make_float4(bi[o0], bi[o0 + 1], bi[o0 + 2], bi[o0 + 3]);
        #pragma unroll
        for (int b = 0; b < TB; b++) {
            float4 a = bv;
            for (int k = s; k < e; k++) {
                const float aw = ae[k];
                const float4 hv = *reinterpret_cast<const float4*>(h + b * STATE + c_nbr_lst[k] * WD + o0);
                a.x = fmaf(aw, hv.x, a.x);
                a.y = fmaf(aw, hv.y, a.y);
                a.z = fmaf(aw, hv.z, a.z);
                a.w = fmaf(aw, hv.w, a.w);
            }
            if (relu) {
                a.x = fmaxf(a.x, 0.f); a.y = fmaxf(a.y, 0.f);
                a.z = fmaxf(a.z, 0.f); a.w = fmaxf(a.w, 0.f);
            }
            *reinterpret_cast<float4*>(dst + b * STATE + n * WD + o0) = a;
        }
    };

    // Hidden-layer per-node matmul, f32x2, bt=6, ot=4.
    // Per chunk: stage acts for 3 batches, load 4 weight rows once, swap act half.
    auto mm64 = [&](const float* __restrict__ src, const float* __restrict__ wgt,
                    float* __restrict__ dst) {
        unsigned long long accL[TB], accH[TB];
        #pragma unroll
        for (int b = 0; b < TB; b++) { accL[b] = 0ull; accH[b] = 0ull; }
        const float* wrow = wgt + n * WD * WD + o0;
        const float* abase = src + n * WD;
        #pragma unroll 2
        for (int i = 0; i < WD; i += 4) {
            const ulonglong2 w0p = __ldg(reinterpret_cast<const ulonglong2*>(wrow + (i + 0) * WD));
            const ulonglong2 w1p = __ldg(reinterpret_cast<const ulonglong2*>(wrow + (i + 1) * WD));
            const ulonglong2 w2p = __ldg(reinterpret_cast<const ulonglong2*>(wrow + (i + 2) * WD));
            const ulonglong2 w3p = __ldg(reinterpret_cast<const ulonglong2*>(wrow + (i + 3) * WD));
            #pragma unroll
            for (int h = 0; h < 2; h++) {        // batch halves: 3 + 3
                float4 xv[3];
                #pragma unroll
                for (int q = 0; q < 3; q++)
                    xv[q] = *reinterpret_cast<const float4*>(abase + (h * 3 + q) * STATE + i);
                #pragma unroll
                for (int q = 0; q < 3; q++) {
                    const int b = h * 3 + q;
                    const unsigned long long x0 = dup2(xv[q].x);
                    fma2(accL[b], x0, w0p.x);
                    fma2(accH[b], x0, w0p.y);
                    const unsigned long long x1 = dup2(xv[q].y);
                    fma2(accL[b], x1, w1p.x);
                    fma2(accH[b], x1, w1p.y);
                    const unsigned long long x2 = dup2(xv[q].z);
                    fma2(accL[b], x2, w2p.x);
                    fma2(accH[b], x2, w2p.y);
                    const unsigned long long x3 = dup2(xv[q].w);
                    fma2(accL[b], x3, w3p.x);
                    fma2(accH[b], x3, w3p.y);
                }
            }
        }
        #pragma unroll
        for (int b = 0; b < TB; b++)
            *reinterpret_cast<ulonglong2*>(dst + b * STATE + n * WD + o0) =
                make_ulonglong2(accL[b], accH[b]);
    };

    agg(bufA, aeff + 0, bias + 0, bufB, true);        // L0 agg
    __syncthreads();
    mm64(bufB, w1, bufA);                              // L1 matmul
    __syncthreads();
    agg(bufA, aeff + 70, bias + WD, bufB, true);       // L1 agg
    __syncthreads();
    mm64(bufB, w2, bufA);                              // L2 matmul
    __syncthreads();
    agg(bufA, aeff + 140, bias + 2 * WD, bufB, true);  // L2 agg
    __syncthreads();

    // ---- Layer 3 matmul: bufB[b][n][0:64] @ w3[n][64][13] -> bufA (stride WD) ----
    if (tid < NN * FOUT) {
        const int n3 = tid / FOUT, o3 = tid - n3 * FOUT;
        float acc[TB];
        #pragma unroll
        for (int b = 0; b < TB; b++) acc[b] = 0.f;
        #pragma unroll 4
        for (int i = 0; i < WD; i++) {
            const float wv = __ldg(w3 + (n3 * WD + i) * FOUT + o3);
            #pragma unroll
            for (int b = 0; b < TB; b++)
                acc[b] = fmaf(bufB[b * STATE + n3 * WD + i], wv, acc[b]);
        }
        #pragma unroll
        for (int b = 0; b < TB; b++)
            bufA[b * STATE + n3 * WD + o3] = acc[b];
    }
    __syncthreads();

    // ---- Layer 3 aggregation + bias, store to global (guarded) ----
    if (tid < NN * FOUT) {
        const int n3 = tid / FOUT, o3 = tid - n3 * FOUT;
        const int s = c_nbr_off[n3], e = c_nbr_off[n3 + 1];
        const float bv3 = bias[3 * WD + o3];
        #pragma unroll
        for (int b = 0; b < TB; b++) {
            float a0 = bv3;
            for (int k = s; k < e; k++)
                a0 = fmaf(aeff[210 + k], bufA[b * STATE + c_nbr_lst[k] * WD + o3], a0);
            if (brow0 + b < B)
                out[(brow0 + b) * (NN * FOUT) + n3 * FOUT + o3] = a0;
        }
    }
}

extern "C" void kernel_launch(void* const* d_in, const int* in_sizes, int n_in,
                              void* d_out, int out_size) {
    const float* x   = (const float*)d_in[0];
    const float* w0  = (const float*)d_in[1];
    const float* w1  = (const float*)d_in[2];
    const float* w2  = (const float*)d_in[3];
    const float* w3  = (const float*)d_in[4];
    const float* aw0 = (const float*)d_in[5];
    const float* aw1 = (const float*)d_in[6];
    const float* aw2 = (const float*)d_in[7];
    const float* aw3 = (const float*)d_in[8];
    const float* b0  = (const float*)d_in[9];
    const float* b1  = (const float*)d_in[10];
    const float* b2  = (const float*)d_in[11];
    const float* b3  = (const float*)d_in[12];
    float* out = (float*)d_out;

    const int B = in_sizes[0] / (NN * FIN);
    const int grid = (B + TB - 1) / TB;
    const size_t smem_bytes =
        (size_t)(2 * TB * STATE + 4 * 70 + 3 * WD + FOUT) * sizeof(float);

    cudaFuncSetAttribute(gnn_fused, cudaFuncAttributeMaxDynamicSharedMemorySize,
                         (int)smem_bytes);
    gnn_fused<<<grid, NT, smem_bytes>>>(x, w0, w1, w2, w3,
                                        aw0, aw1, aw2, aw3,
                                        b0, b1, b2, b3, out, B);
}